// round 16
// baseline (speedup 1.0000x reference)
#include <cuda_runtime.h>
#include <cuda_fp16.h>
#include <mma.h>
#include <cstdint>
#include <cstddef>

using namespace nvcuda;

#define NN 100000
#define NN_PAD 100096
#define HH 128
#define EE 1600000
#define EPP 200000

// ---------------- scratch ----------------
__device__ __half g_xw[(size_t)NN_PAD * HH];
__device__ __half g_h1[(size_t)NN_PAD * HH];
__device__ __half g_h2[(size_t)NN * HH];
__device__ __half g_z[(size_t)NN * HH];
__device__ float  g_dinv[NN];
__device__ int2   g_epair[EE];
__device__ int    g_cnt[NN];
__device__ int    g_fill[NN];
__device__ int    g_rowptr[NN + 1];
__device__ int    g_sflag[256];                 // lookback flags (2 x 128)
__device__ int    g_pcnt[NN];
__device__ int    g_pfill[NN];
__device__ int    g_prow[NN + 1];
__device__ int    g_pnode[NN];
__device__ int    g_is64[1];

// ---------------- streams/events (created pre-main) ----------
static cudaStream_t g_s1 = nullptr;
static cudaEvent_t  g_evA = nullptr, g_evB = nullptr, g_evZ = nullptr, g_evC = nullptr;
static const bool g_init = []() {
    cudaStreamCreateWithFlags(&g_s1, cudaStreamNonBlocking);
    cudaEventCreateWithFlags(&g_evA, cudaEventDisableTiming);
    cudaEventCreateWithFlags(&g_evB, cudaEventDisableTiming);
    cudaEventCreateWithFlags(&g_evZ, cudaEventDisableTiming);
    cudaEventCreateWithFlags(&g_evC, cudaEventDisableTiming);
    return true;
}();

__device__ __forceinline__ int idx_at(const void* __restrict__ p, long long i, int is64) {
    if (is64) return (int)((const long long*)p)[i];
    return ((const int*)p)[i];
}

// ---------------- fused: zero counters + flags + detect index dtype ----------------
__global__ void zero_detect_kernel(int* cnt, int* fill, int* pcnt, int* pfill, int n,
                                   const void* __restrict__ p, int* __restrict__ flag,
                                   int* __restrict__ sflag) {
    if (blockIdx.x == gridDim.x - 1) {
        const int2* q = (const int2*)p;
        __shared__ int any_hi;
        if (threadIdx.x == 0) any_hi = 0;
        __syncthreads();
        for (int i = threadIdx.x; i < 1024; i += blockDim.x)
            if (q[i].y != 0) any_hi = 1;
        __syncthreads();
        if (threadIdx.x == 0) flag[0] = any_hi ? 0 : 1;
        return;
    }
    if (blockIdx.x == 0) sflag[threadIdx.x] = 0;
    int i = blockIdx.x * blockDim.x + threadIdx.x;
    if (i < n) { cnt[i] = 0; fill[i] = 0; pcnt[i] = 0; pfill[i] = 0; }
}

// ---------------- histograms (2 elements per thread) ----------------
__global__ void hist_kernel(const void* __restrict__ idx, long long base,
                            const int* __restrict__ flag, int* __restrict__ cnt, int n) {
    int is64 = flag[0];
    int i = (blockIdx.x * blockDim.x + threadIdx.x) * 2;
    if (i < n)     atomicAdd(&cnt[idx_at(idx, base + i, is64)], 1);
    if (i + 1 < n) atomicAdd(&cnt[idx_at(idx, base + i + 1, is64)], 1);
}

// ---------------- single-pass exclusive scan (decoupled lookback) ----------------
__global__ void scan_onepass_kernel(const int* __restrict__ in, int* __restrict__ rp,
                                    float* __restrict__ dinv, int* __restrict__ fl,
                                    int n, int nb) {
    __shared__ int sh[1024];
    __shared__ int sprefix;
    int tid = threadIdx.x;
    int b = blockIdx.x;
    int i = b * 1024 + tid;
    int v = (i < n) ? in[i] : 0;
    if (dinv != nullptr && i < n)
        dinv[i] = rsqrtf((float)(v + 1));   // +1 self-loop
    sh[tid] = v;
    if (tid == 0) sprefix = 0;
    __syncthreads();
    #pragma unroll
    for (int off = 1; off < 1024; off <<= 1) {
        int t = (tid >= off) ? sh[tid - off] : 0;
        __syncthreads();
        sh[tid] += t;
        __syncthreads();
    }
    int total = sh[1023];
    if (tid == 0) atomicExch(&fl[b], total + 1);
    if (tid < b) {
        int f;
        do { f = *((volatile int*)&fl[tid]); } while (f == 0);
        atomicAdd(&sprefix, f - 1);
    }
    __syncthreads();
    int pre = sprefix;
    if (i < n) rp[i] = pre + sh[tid] - v;
    if (b == nb - 1 && tid == 1023) rp[n] = pre + total;
}

// ---------------- CSR scatters (2 edges/thread) ----------------
__global__ void scatter_edges_kernel(const void* __restrict__ edge, long long ne,
                                     const int* __restrict__ flag,
                                     const int* __restrict__ rowptr, int* __restrict__ fill,
                                     int2* __restrict__ epair,
                                     const float* __restrict__ dinv, int n) {
    int is64 = flag[0];
    int e = (blockIdx.x * blockDim.x + threadIdx.x) * 2;
    #pragma unroll
    for (int u = 0; u < 2; u++) {
        int ee = e + u;
        if (ee < n) {
            int s = idx_at(edge, ee, is64);
            int d = idx_at(edge, ne + ee, is64);
            int p = rowptr[d] + atomicAdd(&fill[d], 1);
            float nm = dinv[s] * dinv[d];
            epair[p] = make_int2(s, __float_as_int(nm));
        }
    }
}

__global__ void scatter_pool_kernel(const void* __restrict__ dict,
                                    const int* __restrict__ flag,
                                    const int* __restrict__ prow, int* __restrict__ pfill,
                                    int* __restrict__ pnode, int n) {
    int is64 = flag[0];
    int v = blockIdx.x * blockDim.x + threadIdx.x;
    if (v < n) {
        int d = idx_at(dict, v, is64);
        int p = prow[d] + atomicAdd(&pfill[d], 1);
        pnode[p] = v;
    }
}

// ---------------- helpers ----------------
__device__ __forceinline__ void load4h(const __half* p, float& a0, float& a1, float& a2, float& a3) {
    uint2 v = *reinterpret_cast<const uint2*>(p);
    half2 h0 = *reinterpret_cast<half2*>(&v.x);
    half2 h1 = *reinterpret_cast<half2*>(&v.y);
    float2 f0 = __half22float2(h0), f1 = __half22float2(h1);
    a0 = f0.x; a1 = f0.y; a2 = f1.x; a3 = f1.y;
}
__device__ __forceinline__ void store4h(__half* p, float a0, float a1, float a2, float a3) {
    half2 h0 = __floats2half2_rn(a0, a1);
    half2 h1 = __floats2half2_rn(a2, a3);
    uint2 u;
    u.x = *reinterpret_cast<unsigned*>(&h0);
    u.y = *reinterpret_cast<unsigned*>(&h1);
    *reinterpret_cast<uint2*>(p) = u;
}

// Dual-node fp16 edge accumulation (two independent chains, 4x unrolled).
__device__ __forceinline__ void agg_pair(const __half* __restrict__ xw, size_t loff,
                                         const int2* __restrict__ epair,
                                         int e0, int end0, int e1, int end1,
                                         float* acc) {
    while (e0 + 4 <= end0 && e1 + 4 <= end1) {
        #pragma unroll
        for (int u = 0; u < 4; u++) {
            int2 p0 = __ldg(epair + e0 + u);
            int2 p1 = __ldg(epair + e1 + u);
            float x0, x1, x2, x3, y0, y1, y2, y3;
            load4h(xw + (size_t)p0.x * 128 + loff, x0, x1, x2, x3);
            load4h(xw + (size_t)p1.x * 128 + loff, y0, y1, y2, y3);
            float n0 = __int_as_float(p0.y), n1 = __int_as_float(p1.y);
            acc[0] += x0 * n0; acc[1] += x1 * n0; acc[2] += x2 * n0; acc[3] += x3 * n0;
            acc[4] += y0 * n1; acc[5] += y1 * n1; acc[6] += y2 * n1; acc[7] += y3 * n1;
        }
        e0 += 4; e1 += 4;
    }
    while (e0 < end0 && e1 < end1) {
        int2 p0 = __ldg(epair + e0);
        int2 p1 = __ldg(epair + e1);
        float x0, x1, x2, x3, y0, y1, y2, y3;
        load4h(xw + (size_t)p0.x * 128 + loff, x0, x1, x2, x3);
        load4h(xw + (size_t)p1.x * 128 + loff, y0, y1, y2, y3);
        float n0 = __int_as_float(p0.y), n1 = __int_as_float(p1.y);
        acc[0] += x0 * n0; acc[1] += x1 * n0; acc[2] += x2 * n0; acc[3] += x3 * n0;
        acc[4] += y0 * n1; acc[5] += y1 * n1; acc[6] += y2 * n1; acc[7] += y3 * n1;
        e0++; e1++;
    }
    #pragma unroll 4
    for (; e0 < end0; e0++) {
        int2 p0 = __ldg(epair + e0);
        float x0, x1, x2, x3;
        load4h(xw + (size_t)p0.x * 128 + loff, x0, x1, x2, x3);
        float n0 = __int_as_float(p0.y);
        acc[0] += x0 * n0; acc[1] += x1 * n0; acc[2] += x2 * n0; acc[3] += x3 * n0;
    }
    #pragma unroll 4
    for (; e1 < end1; e1++) {
        int2 p1 = __ldg(epair + e1);
        float y0, y1, y2, y3;
        load4h(xw + (size_t)p1.x * 128 + loff, y0, y1, y2, y3);
        float n1 = __int_as_float(p1.y);
        acc[4] += y0 * n1; acc[5] += y1 * n1; acc[6] += y2 * n1; acc[7] += y3 * n1;
    }
}

#define AS_STRIDE 136
#define SMEM_BYTES_G1 (128 * AS_STRIDE * 2 + 32 * AS_STRIDE * 2)   // GEMM1: 128-row tile
#define SMEM_BYTES_F  (64 * AS_STRIDE * 2 + 32 * AS_STRIDE * 2)    // fused: 64-row tile (26.1KB)

// ---------------- GEMM phase-2, 256-thread / 128-row variant (GEMM1) ------
__device__ __forceinline__ void gemm_phase2_256(__half (*As)[AS_STRIDE], __half (*Ws)[AS_STRIDE],
                                                float* ebuf, const float* __restrict__ W,
                                                __half* __restrict__ C, int row0, int tid) {
    int warpId = tid >> 5;
    int wm = warpId & 3;
    int wn = warpId >> 2;
    wmma::fragment<wmma::accumulator, 16, 16, 16, float> acc[2][4];
    #pragma unroll
    for (int i = 0; i < 2; i++)
        #pragma unroll
        for (int j = 0; j < 4; j++) wmma::fill_fragment(acc[i][j], 0.0f);

    for (int kt2 = 0; kt2 < 128; kt2 += 32) {
        #pragma unroll
        for (int p = 0; p < 4; p++) {
            int idx = tid + p * 256;
            int r = idx >> 5;
            int c4 = (idx & 31) * 4;
            float4 v = *reinterpret_cast<const float4*>(W + (size_t)(kt2 + r) * 128 + c4);
            *reinterpret_cast<half2*>(&Ws[r][c4])     = __floats2half2_rn(v.x, v.y);
            *reinterpret_cast<half2*>(&Ws[r][c4 + 2]) = __floats2half2_rn(v.z, v.w);
        }
        __syncthreads();
        #pragma unroll
        for (int kk = 0; kk < 2; kk++) {
            int k0 = kt2 + kk * 16;
            wmma::fragment<wmma::matrix_a, 16, 16, 16, __half, wmma::row_major> af[2];
            wmma::fragment<wmma::matrix_b, 16, 16, 16, __half, wmma::row_major> bf[4];
            #pragma unroll
            for (int i = 0; i < 2; i++)
                wmma::load_matrix_sync(af[i], &As[wm * 32 + i * 16][k0], AS_STRIDE);
            #pragma unroll
            for (int j = 0; j < 4; j++)
                wmma::load_matrix_sync(bf[j], &Ws[kk * 16][wn * 64 + j * 16], AS_STRIDE);
            #pragma unroll
            for (int i = 0; i < 2; i++)
                #pragma unroll
                for (int j = 0; j < 4; j++)
                    wmma::mma_sync(acc[i][j], af[i], bf[j], acc[i][j]);
        }
        __syncthreads();
    }
    int er = tid >> 1;
    int ec0 = (tid & 1) * 32;
    #pragma unroll
    for (int p = 0; p < 2; p++) {
        if (wn == p) {
            #pragma unroll
            for (int i = 0; i < 2; i++)
                #pragma unroll
                for (int j = 0; j < 4; j++)
                    wmma::store_matrix_sync(&ebuf[(wm * 32 + i * 16) * 64 + j * 16],
                                            acc[i][j], 64, wmma::mem_row_major);
        }
        __syncthreads();
        const float* src = ebuf + er * 64 + ec0;
        __half* dst = C + (size_t)(row0 + er) * 128 + p * 64 + ec0;
        #pragma unroll
        for (int k = 0; k < 32; k += 2)
            *reinterpret_cast<half2*>(dst + k) = __floats2half2_rn(src[k], src[k + 1]);
        __syncthreads();
    }
}

// ---------------- GEMM1 (persistent grid-stride over 128-row tiles) ----------------
__global__ void gemm16_kernel(const float* __restrict__ A, const float* __restrict__ W,
                              __half* __restrict__ C, int n, int ntiles) {
    __shared__ __align__(16) unsigned char smemRaw[SMEM_BYTES_G1];
    __half (*As)[AS_STRIDE] = reinterpret_cast<__half(*)[AS_STRIDE]>(smemRaw);
    __half (*Ws)[AS_STRIDE] = reinterpret_cast<__half(*)[AS_STRIDE]>(smemRaw + 128 * AS_STRIDE * 2);
    float* ebuf = reinterpret_cast<float*>(smemRaw);
    int tid = threadIdx.x;
    for (int tile = blockIdx.x; tile < ntiles; tile += gridDim.x) {
        int row0 = tile * 128;
        #pragma unroll
        for (int p = 0; p < 16; p++) {
            int idx = tid + p * 256;
            int r = idx >> 5;
            int c4 = (idx & 31) * 4;
            int gr = row0 + r;
            float4 v = make_float4(0.f, 0.f, 0.f, 0.f);
            if (gr < n) v = *reinterpret_cast<const float4*>(A + (size_t)gr * 128 + c4);
            *reinterpret_cast<half2*>(&As[r][c4])     = __floats2half2_rn(v.x, v.y);
            *reinterpret_cast<half2*>(&As[r][c4 + 2]) = __floats2half2_rn(v.z, v.w);
        }
        __syncthreads();
        gemm_phase2_256(As, Ws, ebuf, W, C, row0, tid);
        __syncthreads();
    }
}

// ---------------- FUSED (persistent grid-stride, 256 threads, 64-row tiles) --------
__global__ __launch_bounds__(256)
void agg_gemm_fused_kernel(const __half* __restrict__ xw,
                           const float* __restrict__ b1,
                           const float* __restrict__ W2,
                           __half* __restrict__ C,
                           const int* __restrict__ rowptr,
                           const int2* __restrict__ epair,
                           const float* __restrict__ dinv, int n, int ntiles) {
    __shared__ __align__(16) unsigned char smemRaw[SMEM_BYTES_F];
    __half (*As)[AS_STRIDE] = reinterpret_cast<__half(*)[AS_STRIDE]>(smemRaw);
    __half (*Ws)[AS_STRIDE] = reinterpret_cast<__half(*)[AS_STRIDE]>(smemRaw + 64 * AS_STRIDE * 2);
    float* ebuf = reinterpret_cast<float*>(smemRaw);
    int tid = threadIdx.x;
    int warpId = tid >> 5;
    int lane = tid & 31;
    size_t loff = (size_t)lane * 4;
    float4 bb = *reinterpret_cast<const float4*>(b1 + loff);

    for (int tile = blockIdx.x; tile < ntiles; tile += gridDim.x) {
        int row0 = tile * 64;

        // phase 1: 8 warps x 4 row-pairs (dual chains) = 64 rows
        #pragma unroll 1
        for (int it = 0; it < 4; it++) {
            int lr0 = warpId + it * 16;
            int lr1 = lr0 + 8;
            int v0 = row0 + lr0;
            int v1 = row0 + lr1;
            float acc[8] = {0.f, 0.f, 0.f, 0.f, 0.f, 0.f, 0.f, 0.f};
            int e0 = 0, end0 = 0, e1 = 0, end1 = 0;
            if (v0 < n) { e0 = rowptr[v0]; end0 = rowptr[v0 + 1]; }
            if (v1 < n) { e1 = rowptr[v1]; end1 = rowptr[v1 + 1]; }
            agg_pair(xw, loff, epair, e0, end0, e1, end1, acc);
            if (v0 < n) {
                float di = dinv[v0]; float sw = di * di;
                float f0, f1, f2, f3;
                load4h(xw + (size_t)v0 * 128 + loff, f0, f1, f2, f3);
                acc[0] = fmaxf(acc[0] + f0 * sw + bb.x, 0.f);
                acc[1] = fmaxf(acc[1] + f1 * sw + bb.y, 0.f);
                acc[2] = fmaxf(acc[2] + f2 * sw + bb.z, 0.f);
                acc[3] = fmaxf(acc[3] + f3 * sw + bb.w, 0.f);
            } else { acc[0] = acc[1] = acc[2] = acc[3] = 0.f; }
            if (v1 < n) {
                float di = dinv[v1]; float sw = di * di;
                float f0, f1, f2, f3;
                load4h(xw + (size_t)v1 * 128 + loff, f0, f1, f2, f3);
                acc[4] = fmaxf(acc[4] + f0 * sw + bb.x, 0.f);
                acc[5] = fmaxf(acc[5] + f1 * sw + bb.y, 0.f);
                acc[6] = fmaxf(acc[6] + f2 * sw + bb.z, 0.f);
                acc[7] = fmaxf(acc[7] + f3 * sw + bb.w, 0.f);
            } else { acc[4] = acc[5] = acc[6] = acc[7] = 0.f; }
            *reinterpret_cast<half2*>(&As[lr0][lane * 4])     = __floats2half2_rn(acc[0], acc[1]);
            *reinterpret_cast<half2*>(&As[lr0][lane * 4 + 2]) = __floats2half2_rn(acc[2], acc[3]);
            *reinterpret_cast<half2*>(&As[lr1][lane * 4])     = __floats2half2_rn(acc[4], acc[5]);
            *reinterpret_cast<half2*>(&As[lr1][lane * 4 + 2]) = __floats2half2_rn(acc[6], acc[7]);
        }
        __syncthreads();

        // phase 2: 8 warps in 2(M) x 4(N), warp tile 32x32
        int wm = warpId & 1;
        int wn = warpId >> 1;
        wmma::fragment<wmma::accumulator, 16, 16, 16, float> acc2[2][2];
        #pragma unroll
        for (int i = 0; i < 2; i++)
            #pragma unroll
            for (int j = 0; j < 2; j++) wmma::fill_fragment(acc2[i][j], 0.0f);

        for (int kt2 = 0; kt2 < 128; kt2 += 32) {
            #pragma unroll
            for (int p = 0; p < 4; p++) {
                int idx = tid + p * 256;
                int r = idx >> 5;
                int c4 = (idx & 31) * 4;
                float4 v = *reinterpret_cast<const float4*>(W2 + (size_t)(kt2 + r) * 128 + c4);
                *reinterpret_cast<half2*>(&Ws[r][c4])     = __floats2half2_rn(v.x, v.y);
                *reinterpret_cast<half2*>(&Ws[r][c4 + 2]) = __floats2half2_rn(v.z, v.w);
            }
            __syncthreads();
            #pragma unroll
            for (int kk = 0; kk < 2; kk++) {
                int k0 = kt2 + kk * 16;
                wmma::fragment<wmma::matrix_a, 16, 16, 16, __half, wmma::row_major> af[2];
                wmma::fragment<wmma::matrix_b, 16, 16, 16, __half, wmma::row_major> bf[2];
                #pragma unroll
                for (int i = 0; i < 2; i++)
                    wmma::load_matrix_sync(af[i], &As[wm * 32 + i * 16][k0], AS_STRIDE);
                #pragma unroll
                for (int j = 0; j < 2; j++)
                    wmma::load_matrix_sync(bf[j], &Ws[kk * 16][wn * 32 + j * 16], AS_STRIDE);
                #pragma unroll
                for (int i = 0; i < 2; i++)
                    #pragma unroll
                    for (int j = 0; j < 2; j++)
                        wmma::mma_sync(acc2[i][j], af[i], bf[j], acc2[i][j]);
            }
            __syncthreads();
        }
        // epilogue: two N-half passes through ebuf
        int er = tid >> 2;
        int ec0 = (tid & 3) * 16;
        #pragma unroll
        for (int p = 0; p < 2; p++) {
            if ((wn >> 1) == p) {
                int colbase = (wn & 1) * 32;
                #pragma unroll
                for (int i = 0; i < 2; i++)
                    #pragma unroll
                    for (int j = 0; j < 2; j++)
                        wmma::store_matrix_sync(&ebuf[(wm * 32 + i * 16) * 64 + colbase + j * 16],
                                                acc2[i][j], 64, wmma::mem_row_major);
            }
            __syncthreads();
            const float* src = ebuf + er * 64 + ec0;
            __half* dst = C + (size_t)(row0 + er) * 128 + p * 64 + ec0;
            #pragma unroll
            for (int k = 0; k < 16; k += 2)
                *reinterpret_cast<half2*>(dst + k) = __floats2half2_rn(src[k], src[k + 1]);
            __syncthreads();
        }
    }
}

// ---------------- layer-2 aggregation: persistent, warp per TWO dst nodes ----------
__global__ __launch_bounds__(256)
void agg_warp2_kernel(const __half* __restrict__ xw, __half* __restrict__ out,
                      const float* __restrict__ bias,
                      const int* __restrict__ rowptr, const int2* __restrict__ epair,
                      const float* __restrict__ dinv, int n) {
    int lane = threadIdx.x & 31;
    size_t loff = (size_t)lane * 4;
    float4 bbv = *reinterpret_cast<const float4*>(bias + loff);
    int wstride = (gridDim.x * blockDim.x) >> 5;
    int npairs = (n + 1) / 2;
    for (int w = (blockIdx.x * blockDim.x + threadIdx.x) >> 5; w < npairs; w += wstride) {
        int v0 = 2 * w;
        int v1 = 2 * w + 1;
        float acc[8] = {0.f, 0.f, 0.f, 0.f, 0.f, 0.f, 0.f, 0.f};
        int e0 = rowptr[v0], end0 = rowptr[v0 + 1];
        int e1 = 0, end1 = 0;
        if (v1 < n) { e1 = rowptr[v1]; end1 = rowptr[v1 + 1]; }
        agg_pair(xw, loff, epair, e0, end0, e1, end1, acc);
        {
            float di = dinv[v0]; float sw = di * di;
            float f0, f1, f2, f3;
            load4h(xw + (size_t)v0 * 128 + loff, f0, f1, f2, f3);
            store4h(out + (size_t)v0 * 128 + loff,
                    fmaxf(acc[0] + f0 * sw + bbv.x, 0.f), fmaxf(acc[1] + f1 * sw + bbv.y, 0.f),
                    fmaxf(acc[2] + f2 * sw + bbv.z, 0.f), fmaxf(acc[3] + f3 * sw + bbv.w, 0.f));
        }
        if (v1 < n) {
            float di = dinv[v1]; float sw = di * di;
            float f0, f1, f2, f3;
            load4h(xw + (size_t)v1 * 128 + loff, f0, f1, f2, f3);
            store4h(out + (size_t)v1 * 128 + loff,
                    fmaxf(acc[4] + f0 * sw + bbv.x, 0.f), fmaxf(acc[5] + f1 * sw + bbv.y, 0.f),
                    fmaxf(acc[6] + f2 * sw + bbv.z, 0.f), fmaxf(acc[7] + f3 * sw + bbv.w, 0.f));
        }
    }
}

// ---------------- mean-pool: persistent, warp per segment ----------------
__global__ void pool_warp_kernel(const __half* __restrict__ h, __half* __restrict__ z,
                                 const int* __restrict__ prow, const int* __restrict__ pnode,
                                 int n) {
    int lane = threadIdx.x & 31;
    size_t loff = (size_t)lane * 4;
    int wstride = (gridDim.x * blockDim.x) >> 5;
    for (int w = (blockIdx.x * blockDim.x + threadIdx.x) >> 5; w < n; w += wstride) {
        int beg = prow[w];
        int end = prow[w + 1];
        float a0 = 0.f, a1 = 0.f, a2 = 0.f, a3 = 0.f;
        #pragma unroll 4
        for (int m = beg; m < end; m++) {
            int nd = __ldg(pnode + m);
            float f0, f1, f2, f3;
            load4h(h + (size_t)nd * 128 + loff, f0, f1, f2, f3);
            a0 += f0; a1 += f1; a2 += f2; a3 += f3;
        }
        float inv = 1.0f / fmaxf((float)(end - beg), 1.0f);
        store4h(z + (size_t)w * 128 + loff, a0 * inv, a1 * inv, a2 * inv, a3 * inv);
    }
}

// ---------------- decode: half-warp per edge (16 lanes x 8 features) ----------------
__global__ void decode_kernel(const __half* __restrict__ z,
                              const void* __restrict__ pos,
                              const void* __restrict__ neg,
                              const int* __restrict__ flag,
                              float* __restrict__ out, int ep) {
    int is64 = flag[0];
    int gw = (blockIdx.x * blockDim.x + threadIdx.x) >> 5;   // warp id
    int lane = threadIdx.x & 31;
    int hw = lane >> 4;
    int l16 = lane & 15;
    int total = 2 * ep;
    int e = 2 * gw + hw;
    if (2 * gw >= total) return;
    if (e < total) {
        int a, b;
        if (e < ep) { a = idx_at(pos, e, is64); b = idx_at(pos, (long long)ep + e, is64); }
        else { int q = e - ep; a = idx_at(neg, q, is64); b = idx_at(neg, (long long)ep + q, is64); }
        int c8 = l16 * 8;
        float a0, a1, a2, a3, a4, a5, a6, a7, b0, b1, b2, b3, b4, b5, b6, b7;
        load4h(z + (size_t)a * 128 + c8,     a0, a1, a2, a3);
        load4h(z + (size_t)a * 128 + c8 + 4, a4, a5, a6, a7);
        load4h(z + (size_t)b * 128 + c8,     b0, b1, b2, b3);
        load4h(z + (size_t)b * 128 + c8 + 4, b4, b5, b6, b7);
        float s = a0 * b0 + a1 * b1 + a2 * b2 + a3 * b3
                + a4 * b4 + a5 * b5 + a6 * b6 + a7 * b7;
        s += __shfl_xor_sync(0xffffffffu, s, 8);
        s += __shfl_xor_sync(0xffffffffu, s, 4);
        s += __shfl_xor_sync(0xffffffffu, s, 2);
        s += __shfl_xor_sync(0xffffffffu, s, 1);
        if (l16 == 0) out[e] = s;
    }
}

// ---------------- launch ----------------
extern "C" void kernel_launch(void* const* d_in, const int* in_sizes, int n_in,
                              void* d_out, int out_size) {
    const float* x  = (const float*)d_in[0];
    const float* W1 = (const float*)d_in[1];
    const float* b1 = (const float*)d_in[2];
    const float* W2 = (const float*)d_in[3];
    const float* b2 = (const float*)d_in[4];
    const void*  edge = d_in[5];
    const void*  dict = d_in[6];
    const void*  pos  = d_in[7];
    const void*  neg  = d_in[8];
    float* out = (float*)d_out;

    const int n  = in_sizes[0] / HH;
    const int ne = in_sizes[5] / 2;
    const int ep = in_sizes[7] / 2;

    __half *xw, *h1, *h2, *z;
    float *dinv;
    int2* epair;
    int *cnt, *fill, *rowptr, *sflag, *pcnt, *pfill, *prow, *pnode, *flag;
    cudaGetSymbolAddress((void**)&xw,    g_xw);
    cudaGetSymbolAddress((void**)&h1,    g_h1);
    cudaGetSymbolAddress((void**)&h2,    g_h2);
    cudaGetSymbolAddress((void**)&z,     g_z);
    cudaGetSymbolAddress((void**)&dinv,  g_dinv);
    cudaGetSymbolAddress((void**)&epair, g_epair);
    cudaGetSymbolAddress((void**)&cnt,   g_cnt);
    cudaGetSymbolAddress((void**)&fill,  g_fill);
    cudaGetSymbolAddress((void**)&rowptr,g_rowptr);
    cudaGetSymbolAddress((void**)&sflag, g_sflag);
    cudaGetSymbolAddress((void**)&pcnt,  g_pcnt);
    cudaGetSymbolAddress((void**)&pfill, g_pfill);
    cudaGetSymbolAddress((void**)&prow,  g_prow);
    cudaGetSymbolAddress((void**)&pnode, g_pnode);
    cudaGetSymbolAddress((void**)&flag,  g_is64);

    const int nb1024 = (n + 1023) / 1024;           // 98 (<=128)
    const int nbE2 = (ne / 2 + 255) / 256;
    const int nbN  = (n + 255) / 256;
    const int nbN2 = (n / 2 + 255) / 256;
    const int gemm1_tiles = (n + 127) / 128;        // 782
    const int gemm1_grid  = 296;                    // 2 blocks/SM persistent
    const int fused_tiles = (n + 63) / 64;          // 1563
    const int fused_grid  = 592;                    // ~4 blocks/SM persistent
    const int aggw2_grid  = 592;                    // persistent
    const int poolw_grid  = 592;

    // fork: GEMM1 on s1 (depends only on x, W1)
    cudaEventRecord(g_evA, 0);
    cudaStreamWaitEvent(g_s1, g_evA, 0);
    gemm16_kernel<<<gemm1_grid, 256, 0, g_s1>>>(x, W1, xw, n, gemm1_tiles);
    cudaEventRecord(g_evB, g_s1);

    // default stream: edge-CSR chain
    zero_detect_kernel<<<nbN + 1, 256>>>(cnt, fill, pcnt, pfill, n, edge, flag, sflag);
    cudaEventRecord(g_evZ, 0);
    hist_kernel<<<nbE2, 256>>>(edge, (long long)ne, flag, cnt, ne);
    scan_onepass_kernel<<<nb1024, 1024>>>(cnt, rowptr, dinv, sflag, n, nb1024);
    scatter_edges_kernel<<<nbE2, 256>>>(edge, (long long)ne, flag, rowptr, fill, epair, dinv, ne);

    // fused agg1 + GEMM2 (persistent)
    cudaStreamWaitEvent(0, g_evB, 0);
    agg_gemm_fused_kernel<<<fused_grid, 256>>>(xw, b1, W2, h1, rowptr, epair, dinv, n, fused_tiles);
    // layer-2 aggregation (persistent)
    agg_warp2_kernel<<<aggw2_grid, 256>>>(h1, h2, b2, rowptr, epair, dinv, n);

    // s1: pool CSR prep, overlapped with heavy middle
    cudaStreamWaitEvent(g_s1, g_evZ, 0);
    hist_kernel<<<nbN2, 256, 0, g_s1>>>(dict, 0LL, flag, pcnt, n);
    scan_onepass_kernel<<<nb1024, 1024, 0, g_s1>>>(pcnt, prow, nullptr, sflag + 128, n, nb1024);
    scatter_pool_kernel<<<nbN, 256, 0, g_s1>>>(dict, flag, prow, pfill, pnode, n);
    cudaEventRecord(g_evC, g_s1);

    // mean pool (persistent; needs pool CSR + h2)
    cudaStreamWaitEvent(0, g_evC, 0);
    pool_warp_kernel<<<poolw_grid, 256>>>(h2, z, prow, pnode, n);
    // decode (half-warp per edge)
    int total_edges = 2 * ep;
    int dec_warps = (total_edges + 1) / 2;
    int dec_blocks = (dec_warps * 32 + 255) / 256;
    decode_kernel<<<dec_blocks, 256>>>(z, pos, neg, flag, out, ep);
}

// round 17
// speedup vs baseline: 1.0155x; 1.0155x over previous
#include <cuda_runtime.h>
#include <cuda_fp16.h>
#include <mma.h>
#include <cstdint>
#include <cstddef>

using namespace nvcuda;

#define NN 100000
#define NN_PAD 100096
#define HH 128
#define EE 1600000
#define EPP 200000

// ---------------- scratch ----------------
__device__ __half g_xw[(size_t)NN_PAD * HH];
__device__ __half g_h1[(size_t)NN_PAD * HH];
__device__ __half g_h2[(size_t)NN * HH];
__device__ __half g_z[(size_t)NN * HH];
__device__ float  g_dinv[NN];
__device__ int2   g_epair[EE];
__device__ int    g_cnt[NN];
__device__ int    g_fill[NN];
__device__ int    g_rowptr[NN + 1];
__device__ int    g_sflag[256];                 // lookback flags (2 x 128)
__device__ int    g_pcnt[NN];
__device__ int    g_pfill[NN];
__device__ int    g_prow[NN + 1];
__device__ int    g_pnode[NN];
__device__ int    g_is64[1];

// ---------------- streams/events (created pre-main) ----------
static cudaStream_t g_s1 = nullptr;
static cudaEvent_t  g_evA = nullptr, g_evB = nullptr, g_evZ = nullptr, g_evC = nullptr;
static const bool g_init = []() {
    cudaStreamCreateWithFlags(&g_s1, cudaStreamNonBlocking);
    cudaEventCreateWithFlags(&g_evA, cudaEventDisableTiming);
    cudaEventCreateWithFlags(&g_evB, cudaEventDisableTiming);
    cudaEventCreateWithFlags(&g_evZ, cudaEventDisableTiming);
    cudaEventCreateWithFlags(&g_evC, cudaEventDisableTiming);
    return true;
}();

__device__ __forceinline__ int idx_at(const void* __restrict__ p, long long i, int is64) {
    if (is64) return (int)((const long long*)p)[i];
    return ((const int*)p)[i];
}

// ---------------- fused: zero counters + flags + detect index dtype ----------------
__global__ void zero_detect_kernel(int* cnt, int* fill, int* pcnt, int* pfill, int n,
                                   const void* __restrict__ p, int* __restrict__ flag,
                                   int* __restrict__ sflag) {
    if (blockIdx.x == gridDim.x - 1) {
        const int2* q = (const int2*)p;
        __shared__ int any_hi;
        if (threadIdx.x == 0) any_hi = 0;
        __syncthreads();
        for (int i = threadIdx.x; i < 1024; i += blockDim.x)
            if (q[i].y != 0) any_hi = 1;
        __syncthreads();
        if (threadIdx.x == 0) flag[0] = any_hi ? 0 : 1;
        return;
    }
    if (blockIdx.x == 0) sflag[threadIdx.x] = 0;
    int i = blockIdx.x * blockDim.x + threadIdx.x;
    if (i < n) { cnt[i] = 0; fill[i] = 0; pcnt[i] = 0; pfill[i] = 0; }
}

// ---------------- histograms (2 elements per thread) ----------------
__global__ void hist_kernel(const void* __restrict__ idx, long long base,
                            const int* __restrict__ flag, int* __restrict__ cnt, int n) {
    int is64 = flag[0];
    int i = (blockIdx.x * blockDim.x + threadIdx.x) * 2;
    if (i < n)     atomicAdd(&cnt[idx_at(idx, base + i, is64)], 1);
    if (i + 1 < n) atomicAdd(&cnt[idx_at(idx, base + i + 1, is64)], 1);
}

// ---------------- single-pass exclusive scan (decoupled lookback) ----------------
__global__ void scan_onepass_kernel(const int* __restrict__ in, int* __restrict__ rp,
                                    float* __restrict__ dinv, int* __restrict__ fl,
                                    int n, int nb) {
    __shared__ int sh[1024];
    __shared__ int sprefix;
    int tid = threadIdx.x;
    int b = blockIdx.x;
    int i = b * 1024 + tid;
    int v = (i < n) ? in[i] : 0;
    if (dinv != nullptr && i < n)
        dinv[i] = rsqrtf((float)(v + 1));   // +1 self-loop
    sh[tid] = v;
    if (tid == 0) sprefix = 0;
    __syncthreads();
    #pragma unroll
    for (int off = 1; off < 1024; off <<= 1) {
        int t = (tid >= off) ? sh[tid - off] : 0;
        __syncthreads();
        sh[tid] += t;
        __syncthreads();
    }
    int total = sh[1023];
    if (tid == 0) atomicExch(&fl[b], total + 1);
    if (tid < b) {
        int f;
        do { f = *((volatile int*)&fl[tid]); } while (f == 0);
        atomicAdd(&sprefix, f - 1);
    }
    __syncthreads();
    int pre = sprefix;
    if (i < n) rp[i] = pre + sh[tid] - v;
    if (b == nb - 1 && tid == 1023) rp[n] = pre + total;
}

// ---------------- CSR scatters (2 edges/thread) ----------------
__global__ void scatter_edges_kernel(const void* __restrict__ edge, long long ne,
                                     const int* __restrict__ flag,
                                     const int* __restrict__ rowptr, int* __restrict__ fill,
                                     int2* __restrict__ epair,
                                     const float* __restrict__ dinv, int n) {
    int is64 = flag[0];
    int e = (blockIdx.x * blockDim.x + threadIdx.x) * 2;
    #pragma unroll
    for (int u = 0; u < 2; u++) {
        int ee = e + u;
        if (ee < n) {
            int s = idx_at(edge, ee, is64);
            int d = idx_at(edge, ne + ee, is64);
            int p = rowptr[d] + atomicAdd(&fill[d], 1);
            float nm = dinv[s] * dinv[d];
            epair[p] = make_int2(s, __float_as_int(nm));
        }
    }
}

__global__ void scatter_pool_kernel(const void* __restrict__ dict,
                                    const int* __restrict__ flag,
                                    const int* __restrict__ prow, int* __restrict__ pfill,
                                    int* __restrict__ pnode, int n) {
    int is64 = flag[0];
    int v = blockIdx.x * blockDim.x + threadIdx.x;
    if (v < n) {
        int d = idx_at(dict, v, is64);
        int p = prow[d] + atomicAdd(&pfill[d], 1);
        pnode[p] = v;
    }
}

// ---------------- helpers ----------------
__device__ __forceinline__ void load4h(const __half* p, float& a0, float& a1, float& a2, float& a3) {
    uint2 v = *reinterpret_cast<const uint2*>(p);
    half2 h0 = *reinterpret_cast<half2*>(&v.x);
    half2 h1 = *reinterpret_cast<half2*>(&v.y);
    float2 f0 = __half22float2(h0), f1 = __half22float2(h1);
    a0 = f0.x; a1 = f0.y; a2 = f1.x; a3 = f1.y;
}
__device__ __forceinline__ void store4h(__half* p, float a0, float a1, float a2, float a3) {
    half2 h0 = __floats2half2_rn(a0, a1);
    half2 h1 = __floats2half2_rn(a2, a3);
    uint2 u;
    u.x = *reinterpret_cast<unsigned*>(&h0);
    u.y = *reinterpret_cast<unsigned*>(&h1);
    *reinterpret_cast<uint2*>(p) = u;
}

// Dual-node fp16 edge accumulation (two independent chains, 4x unrolled).
__device__ __forceinline__ void agg_pair(const __half* __restrict__ xw, size_t loff,
                                         const int2* __restrict__ epair,
                                         int e0, int end0, int e1, int end1,
                                         float* acc) {
    while (e0 + 4 <= end0 && e1 + 4 <= end1) {
        #pragma unroll
        for (int u = 0; u < 4; u++) {
            int2 p0 = __ldg(epair + e0 + u);
            int2 p1 = __ldg(epair + e1 + u);
            float x0, x1, x2, x3, y0, y1, y2, y3;
            load4h(xw + (size_t)p0.x * 128 + loff, x0, x1, x2, x3);
            load4h(xw + (size_t)p1.x * 128 + loff, y0, y1, y2, y3);
            float n0 = __int_as_float(p0.y), n1 = __int_as_float(p1.y);
            acc[0] += x0 * n0; acc[1] += x1 * n0; acc[2] += x2 * n0; acc[3] += x3 * n0;
            acc[4] += y0 * n1; acc[5] += y1 * n1; acc[6] += y2 * n1; acc[7] += y3 * n1;
        }
        e0 += 4; e1 += 4;
    }
    while (e0 < end0 && e1 < end1) {
        int2 p0 = __ldg(epair + e0);
        int2 p1 = __ldg(epair + e1);
        float x0, x1, x2, x3, y0, y1, y2, y3;
        load4h(xw + (size_t)p0.x * 128 + loff, x0, x1, x2, x3);
        load4h(xw + (size_t)p1.x * 128 + loff, y0, y1, y2, y3);
        float n0 = __int_as_float(p0.y), n1 = __int_as_float(p1.y);
        acc[0] += x0 * n0; acc[1] += x1 * n0; acc[2] += x2 * n0; acc[3] += x3 * n0;
        acc[4] += y0 * n1; acc[5] += y1 * n1; acc[6] += y2 * n1; acc[7] += y3 * n1;
        e0++; e1++;
    }
    #pragma unroll 4
    for (; e0 < end0; e0++) {
        int2 p0 = __ldg(epair + e0);
        float x0, x1, x2, x3;
        load4h(xw + (size_t)p0.x * 128 + loff, x0, x1, x2, x3);
        float n0 = __int_as_float(p0.y);
        acc[0] += x0 * n0; acc[1] += x1 * n0; acc[2] += x2 * n0; acc[3] += x3 * n0;
    }
    #pragma unroll 4
    for (; e1 < end1; e1++) {
        int2 p1 = __ldg(epair + e1);
        float y0, y1, y2, y3;
        load4h(xw + (size_t)p1.x * 128 + loff, y0, y1, y2, y3);
        float n1 = __int_as_float(p1.y);
        acc[4] += y0 * n1; acc[5] += y1 * n1; acc[6] += y2 * n1; acc[7] += y3 * n1;
    }
}

#define AS_STRIDE 136
#define SMEM_BYTES_G1 (128 * AS_STRIDE * 2 + 32 * AS_STRIDE * 2)   // GEMM1: 128-row tile
#define SMEM_BYTES_F  (64 * AS_STRIDE * 2 + 32 * AS_STRIDE * 2)    // fused: 64-row tile (26.1KB)

// ---------------- GEMM phase-2, 256-thread / 128-row variant (GEMM1) ------
__device__ __forceinline__ void gemm_phase2_256(__half (*As)[AS_STRIDE], __half (*Ws)[AS_STRIDE],
                                                float* ebuf, const float* __restrict__ W,
                                                __half* __restrict__ C, int row0, int tid) {
    int warpId = tid >> 5;
    int wm = warpId & 3;
    int wn = warpId >> 2;
    wmma::fragment<wmma::accumulator, 16, 16, 16, float> acc[2][4];
    #pragma unroll
    for (int i = 0; i < 2; i++)
        #pragma unroll
        for (int j = 0; j < 4; j++) wmma::fill_fragment(acc[i][j], 0.0f);

    for (int kt2 = 0; kt2 < 128; kt2 += 32) {
        #pragma unroll
        for (int p = 0; p < 4; p++) {
            int idx = tid + p * 256;
            int r = idx >> 5;
            int c4 = (idx & 31) * 4;
            float4 v = *reinterpret_cast<const float4*>(W + (size_t)(kt2 + r) * 128 + c4);
            *reinterpret_cast<half2*>(&Ws[r][c4])     = __floats2half2_rn(v.x, v.y);
            *reinterpret_cast<half2*>(&Ws[r][c4 + 2]) = __floats2half2_rn(v.z, v.w);
        }
        __syncthreads();
        #pragma unroll
        for (int kk = 0; kk < 2; kk++) {
            int k0 = kt2 + kk * 16;
            wmma::fragment<wmma::matrix_a, 16, 16, 16, __half, wmma::row_major> af[2];
            wmma::fragment<wmma::matrix_b, 16, 16, 16, __half, wmma::row_major> bf[4];
            #pragma unroll
            for (int i = 0; i < 2; i++)
                wmma::load_matrix_sync(af[i], &As[wm * 32 + i * 16][k0], AS_STRIDE);
            #pragma unroll
            for (int j = 0; j < 4; j++)
                wmma::load_matrix_sync(bf[j], &Ws[kk * 16][wn * 64 + j * 16], AS_STRIDE);
            #pragma unroll
            for (int i = 0; i < 2; i++)
                #pragma unroll
                for (int j = 0; j < 4; j++)
                    wmma::mma_sync(acc[i][j], af[i], bf[j], acc[i][j]);
        }
        __syncthreads();
    }
    int er = tid >> 1;
    int ec0 = (tid & 1) * 32;
    #pragma unroll
    for (int p = 0; p < 2; p++) {
        if (wn == p) {
            #pragma unroll
            for (int i = 0; i < 2; i++)
                #pragma unroll
                for (int j = 0; j < 4; j++)
                    wmma::store_matrix_sync(&ebuf[(wm * 32 + i * 16) * 64 + j * 16],
                                            acc[i][j], 64, wmma::mem_row_major);
        }
        __syncthreads();
        const float* src = ebuf + er * 64 + ec0;
        __half* dst = C + (size_t)(row0 + er) * 128 + p * 64 + ec0;
        #pragma unroll
        for (int k = 0; k < 32; k += 2)
            *reinterpret_cast<half2*>(dst + k) = __floats2half2_rn(src[k], src[k + 1]);
        __syncthreads();
    }
}

// ---------------- GEMM1 (128-row tiles, 256 threads) ----------------
__global__ void gemm16_kernel(const float* __restrict__ A, const float* __restrict__ W,
                              __half* __restrict__ C, int n) {
    __shared__ __align__(16) unsigned char smemRaw[SMEM_BYTES_G1];
    __half (*As)[AS_STRIDE] = reinterpret_cast<__half(*)[AS_STRIDE]>(smemRaw);
    __half (*Ws)[AS_STRIDE] = reinterpret_cast<__half(*)[AS_STRIDE]>(smemRaw + 128 * AS_STRIDE * 2);
    float* ebuf = reinterpret_cast<float*>(smemRaw);
    int tid = threadIdx.x;
    int row0 = blockIdx.x * 128;
    #pragma unroll
    for (int p = 0; p < 16; p++) {
        int idx = tid + p * 256;
        int r = idx >> 5;
        int c4 = (idx & 31) * 4;
        int gr = row0 + r;
        float4 v = make_float4(0.f, 0.f, 0.f, 0.f);
        if (gr < n) v = *reinterpret_cast<const float4*>(A + (size_t)gr * 128 + c4);
        *reinterpret_cast<half2*>(&As[r][c4])     = __floats2half2_rn(v.x, v.y);
        *reinterpret_cast<half2*>(&As[r][c4 + 2]) = __floats2half2_rn(v.z, v.w);
    }
    __syncthreads();
    gemm_phase2_256(As, Ws, ebuf, W, C, row0, tid);
}

// ---------------- FUSED (persistent grid-stride, 256 threads, 64-row tiles) --------
// Per tile: h1tile = relu(agg(xw)+b1); C[64,128] = h1tile @ W2
__global__ __launch_bounds__(256)
void agg_gemm_fused_kernel(const __half* __restrict__ xw,
                           const float* __restrict__ b1,
                           const float* __restrict__ W2,
                           __half* __restrict__ C,
                           const int* __restrict__ rowptr,
                           const int2* __restrict__ epair,
                           const float* __restrict__ dinv, int n, int ntiles) {
    __shared__ __align__(16) unsigned char smemRaw[SMEM_BYTES_F];
    __half (*As)[AS_STRIDE] = reinterpret_cast<__half(*)[AS_STRIDE]>(smemRaw);
    __half (*Ws)[AS_STRIDE] = reinterpret_cast<__half(*)[AS_STRIDE]>(smemRaw + 64 * AS_STRIDE * 2);
    float* ebuf = reinterpret_cast<float*>(smemRaw);       // 64x64 fp32 (aliases As)
    int tid = threadIdx.x;
    int warpId = tid >> 5;            // 0..7
    int lane = tid & 31;
    size_t loff = (size_t)lane * 4;
    float4 bb = *reinterpret_cast<const float4*>(b1 + loff);

    for (int tile = blockIdx.x; tile < ntiles; tile += gridDim.x) {
        int row0 = tile * 64;

        // phase 1: 8 warps x 4 row-pairs (dual chains) = 64 rows
        #pragma unroll 1
        for (int it = 0; it < 4; it++) {
            int lr0 = warpId + it * 16;
            int lr1 = lr0 + 8;
            int v0 = row0 + lr0;
            int v1 = row0 + lr1;
            float acc[8] = {0.f, 0.f, 0.f, 0.f, 0.f, 0.f, 0.f, 0.f};
            int e0 = 0, end0 = 0, e1 = 0, end1 = 0;
            if (v0 < n) { e0 = rowptr[v0]; end0 = rowptr[v0 + 1]; }
            if (v1 < n) { e1 = rowptr[v1]; end1 = rowptr[v1 + 1]; }
            agg_pair(xw, loff, epair, e0, end0, e1, end1, acc);
            if (v0 < n) {
                float di = dinv[v0]; float sw = di * di;
                float f0, f1, f2, f3;
                load4h(xw + (size_t)v0 * 128 + loff, f0, f1, f2, f3);
                acc[0] = fmaxf(acc[0] + f0 * sw + bb.x, 0.f);
                acc[1] = fmaxf(acc[1] + f1 * sw + bb.y, 0.f);
                acc[2] = fmaxf(acc[2] + f2 * sw + bb.z, 0.f);
                acc[3] = fmaxf(acc[3] + f3 * sw + bb.w, 0.f);
            } else { acc[0] = acc[1] = acc[2] = acc[3] = 0.f; }
            if (v1 < n) {
                float di = dinv[v1]; float sw = di * di;
                float f0, f1, f2, f3;
                load4h(xw + (size_t)v1 * 128 + loff, f0, f1, f2, f3);
                acc[4] = fmaxf(acc[4] + f0 * sw + bb.x, 0.f);
                acc[5] = fmaxf(acc[5] + f1 * sw + bb.y, 0.f);
                acc[6] = fmaxf(acc[6] + f2 * sw + bb.z, 0.f);
                acc[7] = fmaxf(acc[7] + f3 * sw + bb.w, 0.f);
            } else { acc[4] = acc[5] = acc[6] = acc[7] = 0.f; }
            *reinterpret_cast<half2*>(&As[lr0][lane * 4])     = __floats2half2_rn(acc[0], acc[1]);
            *reinterpret_cast<half2*>(&As[lr0][lane * 4 + 2]) = __floats2half2_rn(acc[2], acc[3]);
            *reinterpret_cast<half2*>(&As[lr1][lane * 4])     = __floats2half2_rn(acc[4], acc[5]);
            *reinterpret_cast<half2*>(&As[lr1][lane * 4 + 2]) = __floats2half2_rn(acc[6], acc[7]);
        }
        __syncthreads();

        // phase 2: 8 warps in 2(M) x 4(N), warp tile 32x32
        int wm = warpId & 1;
        int wn = warpId >> 1;
        wmma::fragment<wmma::accumulator, 16, 16, 16, float> acc2[2][2];
        #pragma unroll
        for (int i = 0; i < 2; i++)
            #pragma unroll
            for (int j = 0; j < 2; j++) wmma::fill_fragment(acc2[i][j], 0.0f);

        for (int kt2 = 0; kt2 < 128; kt2 += 32) {
            #pragma unroll
            for (int p = 0; p < 4; p++) {
                int idx = tid + p * 256;
                int r = idx >> 5;
                int c4 = (idx & 31) * 4;
                float4 v = *reinterpret_cast<const float4*>(W2 + (size_t)(kt2 + r) * 128 + c4);
                *reinterpret_cast<half2*>(&Ws[r][c4])     = __floats2half2_rn(v.x, v.y);
                *reinterpret_cast<half2*>(&Ws[r][c4 + 2]) = __floats2half2_rn(v.z, v.w);
            }
            __syncthreads();
            #pragma unroll
            for (int kk = 0; kk < 2; kk++) {
                int k0 = kt2 + kk * 16;
                wmma::fragment<wmma::matrix_a, 16, 16, 16, __half, wmma::row_major> af[2];
                wmma::fragment<wmma::matrix_b, 16, 16, 16, __half, wmma::row_major> bf[2];
                #pragma unroll
                for (int i = 0; i < 2; i++)
                    wmma::load_matrix_sync(af[i], &As[wm * 32 + i * 16][k0], AS_STRIDE);
                #pragma unroll
                for (int j = 0; j < 2; j++)
                    wmma::load_matrix_sync(bf[j], &Ws[kk * 16][wn * 32 + j * 16], AS_STRIDE);
                #pragma unroll
                for (int i = 0; i < 2; i++)
                    #pragma unroll
                    for (int j = 0; j < 2; j++)
                        wmma::mma_sync(acc2[i][j], af[i], bf[j], acc2[i][j]);
            }
            __syncthreads();
        }
        // epilogue: two N-half passes through ebuf
        int er = tid >> 2;
        int ec0 = (tid & 3) * 16;
        #pragma unroll
        for (int p = 0; p < 2; p++) {
            if ((wn >> 1) == p) {
                int colbase = (wn & 1) * 32;
                #pragma unroll
                for (int i = 0; i < 2; i++)
                    #pragma unroll
                    for (int j = 0; j < 2; j++)
                        wmma::store_matrix_sync(&ebuf[(wm * 32 + i * 16) * 64 + colbase + j * 16],
                                                acc2[i][j], 64, wmma::mem_row_major);
            }
            __syncthreads();
            const float* src = ebuf + er * 64 + ec0;
            __half* dst = C + (size_t)(row0 + er) * 128 + p * 64 + ec0;
            #pragma unroll
            for (int k = 0; k < 16; k += 2)
                *reinterpret_cast<half2*>(dst + k) = __floats2half2_rn(src[k], src[k + 1]);
            __syncthreads();
        }
    }
}

// ---------------- layer-2 aggregation: warp per TWO dst nodes (dual chain) ----------
__global__ __launch_bounds__(256)
void agg_warp2_kernel(const __half* __restrict__ xw, __half* __restrict__ out,
                      const float* __restrict__ bias,
                      const int* __restrict__ rowptr, const int2* __restrict__ epair,
                      const float* __restrict__ dinv, int n) {
    int w = (blockIdx.x * blockDim.x + threadIdx.x) >> 5;
    int lane = threadIdx.x & 31;
    int v0 = 2 * w;
    int v1 = 2 * w + 1;
    if (v0 >= n) return;
    size_t loff = (size_t)lane * 4;
    float acc[8] = {0.f, 0.f, 0.f, 0.f, 0.f, 0.f, 0.f, 0.f};
    int e0 = rowptr[v0], end0 = rowptr[v0 + 1];
    int e1 = 0, end1 = 0;
    if (v1 < n) { e1 = rowptr[v1]; end1 = rowptr[v1 + 1]; }
    agg_pair(xw, loff, epair, e0, end0, e1, end1, acc);
    float4 bbv = *reinterpret_cast<const float4*>(bias + loff);
    {
        float di = dinv[v0]; float sw = di * di;
        float f0, f1, f2, f3;
        load4h(xw + (size_t)v0 * 128 + loff, f0, f1, f2, f3);
        store4h(out + (size_t)v0 * 128 + loff,
                fmaxf(acc[0] + f0 * sw + bbv.x, 0.f), fmaxf(acc[1] + f1 * sw + bbv.y, 0.f),
                fmaxf(acc[2] + f2 * sw + bbv.z, 0.f), fmaxf(acc[3] + f3 * sw + bbv.w, 0.f));
    }
    if (v1 < n) {
        float di = dinv[v1]; float sw = di * di;
        float f0, f1, f2, f3;
        load4h(xw + (size_t)v1 * 128 + loff, f0, f1, f2, f3);
        store4h(out + (size_t)v1 * 128 + loff,
                fmaxf(acc[4] + f0 * sw + bbv.x, 0.f), fmaxf(acc[5] + f1 * sw + bbv.y, 0.f),
                fmaxf(acc[6] + f2 * sw + bbv.z, 0.f), fmaxf(acc[7] + f3 * sw + bbv.w, 0.f));
    }
}

// ---------------- mean-pool: warp per segment ----------------
__global__ void pool_warp_kernel(const __half* __restrict__ h, __half* __restrict__ z,
                                 const int* __restrict__ prow, const int* __restrict__ pnode,
                                 int n) {
    int w = (blockIdx.x * blockDim.x + threadIdx.x) >> 5;
    int lane = threadIdx.x & 31;
    if (w >= n) return;
    int beg = prow[w];
    int end = prow[w + 1];
    size_t loff = (size_t)lane * 4;
    float a0 = 0.f, a1 = 0.f, a2 = 0.f, a3 = 0.f;
    #pragma unroll 4
    for (int m = beg; m < end; m++) {
        int nd = __ldg(pnode + m);
        float f0, f1, f2, f3;
        load4h(h + (size_t)nd * 128 + loff, f0, f1, f2, f3);
        a0 += f0; a1 += f1; a2 += f2; a3 += f3;
    }
    float inv = 1.0f / fmaxf((float)(end - beg), 1.0f);
    store4h(z + (size_t)w * 128 + loff, a0 * inv, a1 * inv, a2 * inv, a3 * inv);
}

// ---------------- decode: half-warp per edge (16 lanes x 8 features) ----------------
__global__ void decode_kernel(const __half* __restrict__ z,
                              const void* __restrict__ pos,
                              const void* __restrict__ neg,
                              const int* __restrict__ flag,
                              float* __restrict__ out, int ep) {
    int is64 = flag[0];
    int gw = (blockIdx.x * blockDim.x + threadIdx.x) >> 5;   // warp id
    int lane = threadIdx.x & 31;
    int hw = lane >> 4;               // half-warp 0/1
    int l16 = lane & 15;
    int total = 2 * ep;
    int e = 2 * gw + hw;              // edge for this half-warp
    if (2 * gw >= total) return;      // warp-uniform exit
    if (e < total) {
        int a, b;
        if (e < ep) { a = idx_at(pos, e, is64); b = idx_at(pos, (long long)ep + e, is64); }
        else { int q = e - ep; a = idx_at(neg, q, is64); b = idx_at(neg, (long long)ep + q, is64); }
        int c8 = l16 * 8;             // 8 features per lane
        float a0, a1, a2, a3, a4, a5, a6, a7, b0, b1, b2, b3, b4, b5, b6, b7;
        load4h(z + (size_t)a * 128 + c8,     a0, a1, a2, a3);
        load4h(z + (size_t)a * 128 + c8 + 4, a4, a5, a6, a7);
        load4h(z + (size_t)b * 128 + c8,     b0, b1, b2, b3);
        load4h(z + (size_t)b * 128 + c8 + 4, b4, b5, b6, b7);
        float s = a0 * b0 + a1 * b1 + a2 * b2 + a3 * b3
                + a4 * b4 + a5 * b5 + a6 * b6 + a7 * b7;
        // reduce within the 16-lane half-warp
        s += __shfl_xor_sync(0xffffffffu, s, 8);
        s += __shfl_xor_sync(0xffffffffu, s, 4);
        s += __shfl_xor_sync(0xffffffffu, s, 2);
        s += __shfl_xor_sync(0xffffffffu, s, 1);
        if (l16 == 0) out[e] = s;
    }
}

// ---------------- launch ----------------
extern "C" void kernel_launch(void* const* d_in, const int* in_sizes, int n_in,
                              void* d_out, int out_size) {
    const float* x  = (const float*)d_in[0];
    const float* W1 = (const float*)d_in[1];
    const float* b1 = (const float*)d_in[2];
    const float* W2 = (const float*)d_in[3];
    const float* b2 = (const float*)d_in[4];
    const void*  edge = d_in[5];
    const void*  dict = d_in[6];
    const void*  pos  = d_in[7];
    const void*  neg  = d_in[8];
    float* out = (float*)d_out;

    const int n  = in_sizes[0] / HH;
    const int ne = in_sizes[5] / 2;
    const int ep = in_sizes[7] / 2;

    __half *xw, *h1, *h2, *z;
    float *dinv;
    int2* epair;
    int *cnt, *fill, *rowptr, *sflag, *pcnt, *pfill, *prow, *pnode, *flag;
    cudaGetSymbolAddress((void**)&xw,    g_xw);
    cudaGetSymbolAddress((void**)&h1,    g_h1);
    cudaGetSymbolAddress((void**)&h2,    g_h2);
    cudaGetSymbolAddress((void**)&z,     g_z);
    cudaGetSymbolAddress((void**)&dinv,  g_dinv);
    cudaGetSymbolAddress((void**)&epair, g_epair);
    cudaGetSymbolAddress((void**)&cnt,   g_cnt);
    cudaGetSymbolAddress((void**)&fill,  g_fill);
    cudaGetSymbolAddress((void**)&rowptr,g_rowptr);
    cudaGetSymbolAddress((void**)&sflag, g_sflag);
    cudaGetSymbolAddress((void**)&pcnt,  g_pcnt);
    cudaGetSymbolAddress((void**)&pfill, g_pfill);
    cudaGetSymbolAddress((void**)&prow,  g_prow);
    cudaGetSymbolAddress((void**)&pnode, g_pnode);
    cudaGetSymbolAddress((void**)&flag,  g_is64);

    const int nb1024 = (n + 1023) / 1024;           // 98 (<=128)
    const int nbE2 = (ne / 2 + 255) / 256;
    const int nbN  = (n + 255) / 256;
    const int nbN2 = (n / 2 + 255) / 256;
    const int gemm1_blocks = (n + 127) / 128;       // 782
    const int fused_tiles  = (n + 63) / 64;         // 1563
    const int fused_grid   = 592;                   // ~4 blocks/SM (persistent)
    const int aggw2_blocks = ((n + 1) / 2 + 7) / 8;
    const int poolw_blocks = (n + 7) / 8;

    // fork: GEMM1 on s1 (depends only on x, W1)
    cudaEventRecord(g_evA, 0);
    cudaStreamWaitEvent(g_s1, g_evA, 0);
    gemm16_kernel<<<gemm1_blocks, 256, 0, g_s1>>>(x, W1, xw, n);
    cudaEventRecord(g_evB, g_s1);

    // default stream: edge-CSR chain
    zero_detect_kernel<<<nbN + 1, 256>>>(cnt, fill, pcnt, pfill, n, edge, flag, sflag);
    cudaEventRecord(g_evZ, 0);
    hist_kernel<<<nbE2, 256>>>(edge, (long long)ne, flag, cnt, ne);
    scan_onepass_kernel<<<nb1024, 1024>>>(cnt, rowptr, dinv, sflag, n, nb1024);
    scatter_edges_kernel<<<nbE2, 256>>>(edge, (long long)ne, flag, rowptr, fill, epair, dinv, ne);

    // fused agg1 + GEMM2 (persistent grid-stride over 64-row tiles)
    cudaStreamWaitEvent(0, g_evB, 0);
    agg_gemm_fused_kernel<<<fused_grid, 256>>>(xw, b1, W2, h1, rowptr, epair, dinv, n, fused_tiles);
    // layer-2 aggregation (dual-chain)
    agg_warp2_kernel<<<aggw2_blocks, 256>>>(h1, h2, b2, rowptr, epair, dinv, n);

    // s1: pool CSR prep, overlapped with heavy middle
    cudaStreamWaitEvent(g_s1, g_evZ, 0);
    hist_kernel<<<nbN2, 256, 0, g_s1>>>(dict, 0LL, flag, pcnt, n);
    scan_onepass_kernel<<<nb1024, 1024, 0, g_s1>>>(pcnt, prow, nullptr, sflag + 128, n, nb1024);
    scatter_pool_kernel<<<nbN, 256, 0, g_s1>>>(dict, flag, prow, pfill, pnode, n);
    cudaEventRecord(g_evC, g_s1);

    // mean pool (needs pool CSR + h2)
    cudaStreamWaitEvent(0, g_evC, 0);
    pool_warp_kernel<<<poolw_blocks, 256>>>(h2, z, prow, pnode, n);
    // decode (half-warp per edge)
    int total_edges = 2 * ep;
    int dec_warps = (total_edges + 1) / 2;
    int dec_blocks = (dec_warps * 32 + 255) / 256;
    decode_kernel<<<dec_blocks, 256>>>(z, pos, neg, flag, out, ep);
}